// round 1
// baseline (speedup 1.0000x reference)
#include <cuda_runtime.h>
#include <math.h>

#define NN 20000
#define EE 160000
#define DD 512
#define HH 8
#define CC 64
#define LL 7
#define ND (NN*DD)

// ---------------- scratch (device globals; no allocation allowed) ----------
__device__ float    g_h[ND];        // residual stream
__device__ float    g_z[ND];        // bn+relu output
__device__ float    g_lin[ND];      // per-layer GEMM output (h_l)
__device__ float    g_agg[ND];      // aggregation output (layers 1..6)
__device__ float    g_sc_src[NN*HH];
__device__ float    g_sc_dst[NN*HH];
__device__ unsigned g_amax[NN*HH];  // order-encoded float max
__device__ float    g_den[NN*HH];
__device__ float    g_ex[EE*HH];
__device__ float    g_sum[DD];
__device__ float    g_sq[DD];
__device__ float    g_mu[DD];
__device__ float    g_rstd[DD];

__device__ __forceinline__ float lrelu(float v) { return v > 0.f ? v : 0.2f * v; }
__device__ __forceinline__ unsigned fenc(float f) {
    unsigned u = __float_as_uint(f);
    return (u & 0x80000000u) ? ~u : (u | 0x80000000u);
}
__device__ __forceinline__ float fdec(unsigned u) {
    return (u & 0x80000000u) ? __uint_as_float(u ^ 0x80000000u) : __uint_as_float(~u);
}

// ---------------- SGEMM: g_lin = A[NN,512] @ B[512,512] --------------------
// 64x64 tile, BK=16, 256 threads, 4x4 per thread.
__global__ void sgemm64(const float* __restrict__ A, const float* __restrict__ B) {
    __shared__ float As[16][64];
    __shared__ float Bs[16][64];
    int tid = threadIdx.x;
    int tx = tid & 15, ty = tid >> 4;
    int row0 = blockIdx.y * 64;
    int col0 = blockIdx.x * 64;
    float acc[4][4] = {};
    int ar = tid >> 2;          // 0..63
    int ak = (tid & 3) * 4;     // 0,4,8,12
    int bk = tid >> 4;          // 0..15
    int bc = (tid & 15) * 4;    // 0..60

    for (int k0 = 0; k0 < 512; k0 += 16) {
        int arow = row0 + ar;
        float4 av = make_float4(0.f, 0.f, 0.f, 0.f);
        if (arow < NN) av = *(const float4*)&A[arow * 512 + k0 + ak];
        As[ak + 0][ar] = av.x; As[ak + 1][ar] = av.y;
        As[ak + 2][ar] = av.z; As[ak + 3][ar] = av.w;
        float4 bv = *(const float4*)&B[(k0 + bk) * 512 + col0 + bc];
        *(float4*)&Bs[bk][bc] = bv;
        __syncthreads();
#pragma unroll
        for (int k = 0; k < 16; k++) {
            float4 ra = *(const float4*)&As[k][ty * 4];
            float4 rb = *(const float4*)&Bs[k][tx * 4];
            float a_[4] = { ra.x, ra.y, ra.z, ra.w };
            float b_[4] = { rb.x, rb.y, rb.z, rb.w };
#pragma unroll
            for (int i = 0; i < 4; i++)
#pragma unroll
                for (int j = 0; j < 4; j++)
                    acc[i][j] += a_[i] * b_[j];
        }
        __syncthreads();
    }
#pragma unroll
    for (int i = 0; i < 4; i++) {
        int r = row0 + ty * 4 + i;
        if (r < NN) {
            float4 v = make_float4(acc[i][0], acc[i][1], acc[i][2], acc[i][3]);
            *(float4*)&g_lin[r * 512 + col0 + tx * 4] = v;
        }
    }
}

// ---------------- attention scores: per (node, head) dot over C=64 ---------
__global__ void scores_kernel(const float* __restrict__ asrc, const float* __restrict__ adst) {
    int n = blockIdx.x;
    int w = threadIdx.x >> 5;   // head (8 warps = 8 heads)
    int lane = threadIdx.x & 31;
    const float* hp = g_lin + n * 512 + w * 64;
    float v0 = hp[lane], v1 = hp[lane + 32];
    float ss = v0 * asrc[w * 64 + lane] + v1 * asrc[w * 64 + lane + 32];
    float sd = v0 * adst[w * 64 + lane] + v1 * adst[w * 64 + lane + 32];
#pragma unroll
    for (int o = 16; o; o >>= 1) {
        ss += __shfl_xor_sync(0xffffffffu, ss, o);
        sd += __shfl_xor_sync(0xffffffffu, sd, o);
    }
    if (!lane) { g_sc_src[n * 8 + w] = ss; g_sc_dst[n * 8 + w] = sd; }
}

// init amax with self-loop alpha
__global__ void init_max_kernel() {
    int i = blockIdx.x * blockDim.x + threadIdx.x;
    if (i < NN * HH) {
        float a = lrelu(g_sc_src[i] + g_sc_dst[i]);
        g_amax[i] = fenc(a);
    }
}

__global__ void edge_max_kernel(const int* __restrict__ ei) {
    int e = blockIdx.x * blockDim.x + threadIdx.x;
    if (e >= EE) return;
    int s = ei[e], d = ei[EE + e];
#pragma unroll
    for (int h = 0; h < 8; h++) {
        float a = lrelu(g_sc_src[s * 8 + h] + g_sc_dst[d * 8 + h]);
        atomicMax(&g_amax[d * 8 + h], fenc(a));
    }
}

// init den with self-loop exp term
__global__ void init_den_kernel() {
    int i = blockIdx.x * blockDim.x + threadIdx.x;
    if (i < NN * HH) {
        float a = lrelu(g_sc_src[i] + g_sc_dst[i]);
        g_den[i] = expf(a - fdec(g_amax[i]));
    }
}

__global__ void edge_exp_kernel(const int* __restrict__ ei) {
    int e = blockIdx.x * blockDim.x + threadIdx.x;
    if (e >= EE) return;
    int s = ei[e], d = ei[EE + e];
#pragma unroll
    for (int h = 0; h < 8; h++) {
        float a = lrelu(g_sc_src[s * 8 + h] + g_sc_dst[d * 8 + h]);
        float ex = expf(a - fdec(g_amax[d * 8 + h]));
        g_ex[e * 8 + h] = ex;
        atomicAdd(&g_den[d * 8 + h], ex);
    }
}

// out[n,d] = bias[d] + w_loop * h_l[n,d]
__global__ void init_out_kernel(const float* __restrict__ bias, float* __restrict__ outp) {
    int i = blockIdx.x * blockDim.x + threadIdx.x;   // exactly ND threads
    int n = i >> 9;
    int dd = i & 511;
    int h = dd >> 6;
    float a = lrelu(g_sc_src[n * 8 + h] + g_sc_dst[n * 8 + h]);
    float wl = expf(a - fdec(g_amax[n * 8 + h])) / (g_den[n * 8 + h] + 1e-16f);
    outp[i] = bias[dd] + wl * g_lin[i];
}

// one warp per edge: out[dst] += w_h * h_l[src]
__global__ void edge_agg_kernel(const int* __restrict__ ei, float* __restrict__ outp) {
    int e = blockIdx.x * 8 + (threadIdx.x >> 5);
    int lane = threadIdx.x & 31;
    if (e >= EE) return;
    int s = ei[e], d = ei[EE + e];
    float w[8];
#pragma unroll
    for (int h = 0; h < 8; h++)
        w[h] = g_ex[e * 8 + h] / (g_den[d * 8 + h] + 1e-16f);
    const float* hs = g_lin + s * 512;
    float* od = outp + d * 512;
#pragma unroll
    for (int i = 0; i < 16; i++) {
        int dd = i * 32 + lane;
        atomicAdd(&od[dd], w[i >> 1] * hs[dd]);
    }
}

__global__ void add_kernel() {
    int i = blockIdx.x * blockDim.x + threadIdx.x;
    g_h[i] += g_agg[i];
}

// 200 blocks x 100 rows each: per-column partial sums
__global__ void bn_partial_kernel() {
    int t = threadIdx.x;            // 0..255
    int row0 = blockIdx.x * 100;
    float s0 = 0.f, s1 = 0.f, q0 = 0.f, q1 = 0.f;
    for (int r = 0; r < 100; r++) {
        const float* p = g_h + (size_t)(row0 + r) * 512;
        float a = p[t], b = p[t + 256];
        s0 += a; s1 += b; q0 += a * a; q1 += b * b;
    }
    atomicAdd(&g_sum[t], s0);       atomicAdd(&g_sum[t + 256], s1);
    atomicAdd(&g_sq[t], q0);        atomicAdd(&g_sq[t + 256], q1);
}

__global__ void bn_finalize_kernel() {
    int d = threadIdx.x;
    float mu = g_sum[d] * (1.f / NN);
    float var = g_sq[d] * (1.f / NN) - mu * mu;
    g_mu[d] = mu;
    g_rstd[d] = rsqrtf(var + 1e-5f);
}

__global__ void bn_relu_kernel(const float* __restrict__ gamma, const float* __restrict__ beta) {
    int i = blockIdx.x * blockDim.x + threadIdx.x;
    int d = i & 511;
    float v = gamma[d] * (g_h[i] - g_mu[d]) * g_rstd[d] + beta[d];
    g_z[i] = v > 0.f ? v : 0.f;
}

// one warp per node: out[n] = dot(z[n,:], lin_w) + lin_b
__global__ void final_kernel(const float* __restrict__ lw, const float* __restrict__ lb,
                             float* __restrict__ out) {
    int n = blockIdx.x * 8 + (threadIdx.x >> 5);
    int lane = threadIdx.x & 31;
    if (n >= NN) return;
    const float* zp = g_z + (size_t)n * 512;
    float s = 0.f;
#pragma unroll
    for (int i = 0; i < 16; i++) {
        int dd = i * 32 + lane;
        s += zp[dd] * lw[dd];
    }
#pragma unroll
    for (int o = 16; o; o >>= 1) s += __shfl_xor_sync(0xffffffffu, s, o);
    if (!lane) out[n] = s + lb[0];
}

// ---------------------------------------------------------------------------
extern "C" void kernel_launch(void* const* d_in, const int* in_sizes, int n_in,
                              void* d_out, int out_size) {
    (void)in_sizes; (void)n_in; (void)out_size;
    const float* x     = (const float*)d_in[0];
    const int*   ei    = (const int*)d_in[1];
    const float* Ws    = (const float*)d_in[2];
    const float* asrc  = (const float*)d_in[3];
    const float* adst  = (const float*)d_in[4];
    const float* cbias = (const float*)d_in[5];
    const float* gamma = (const float*)d_in[6];
    const float* beta  = (const float*)d_in[7];
    const float* lw    = (const float*)d_in[8];
    const float* lb    = (const float*)d_in[9];
    float* out = (float*)d_out;

    float *p_h, *p_z, *p_agg, *p_sum, *p_sq;
    cudaGetSymbolAddress((void**)&p_h,   g_h);
    cudaGetSymbolAddress((void**)&p_z,   g_z);
    cudaGetSymbolAddress((void**)&p_agg, g_agg);
    cudaGetSymbolAddress((void**)&p_sum, g_sum);
    cudaGetSymbolAddress((void**)&p_sq,  g_sq);

    const int TB = 256;
    const int GRID_NH = (NN * HH + TB - 1) / TB;   // 625
    const int GRID_E  = (EE + TB - 1) / TB;        // 625
    const int GRID_ND = ND / TB;                   // 40000 (ND divisible)
    const dim3 GEMM_GRID(8, (NN + 63) / 64);       // (8, 313)

    auto gat = [&](const float* zin, int l, float* outbuf) {
        sgemm64<<<GEMM_GRID, TB>>>(zin, Ws + (size_t)l * 512 * 512);
        scores_kernel<<<NN, TB>>>(asrc + l * HH * CC, adst + l * HH * CC);
        init_max_kernel<<<GRID_NH, TB>>>();
        edge_max_kernel<<<GRID_E, TB>>>(ei);
        init_den_kernel<<<GRID_NH, TB>>>();
        edge_exp_kernel<<<GRID_E, TB>>>(ei);
        init_out_kernel<<<GRID_ND, TB>>>(cbias + l * 512, outbuf);
        edge_agg_kernel<<<EE / 8, TB>>>(ei, outbuf);
    };

    // layer 0: h = gat(x)
    gat(x, 0, p_h);

    // layers 1..6: h = h + gat(relu(bn(h, gamma_l, beta_l)))
    for (int l = 1; l < LL; l++) {
        cudaMemsetAsync(p_sum, 0, DD * sizeof(float));
        cudaMemsetAsync(p_sq,  0, DD * sizeof(float));
        bn_partial_kernel<<<200, TB>>>();
        bn_finalize_kernel<<<1, 512>>>();
        bn_relu_kernel<<<GRID_ND, TB>>>(gamma + l * 512, beta + l * 512);
        gat(p_z, l, p_agg);
        add_kernel<<<GRID_ND, TB>>>();
    }

    // final: relu(bn(h, gamma_0, beta_0)) @ lin_w + lin_b
    cudaMemsetAsync(p_sum, 0, DD * sizeof(float));
    cudaMemsetAsync(p_sq,  0, DD * sizeof(float));
    bn_partial_kernel<<<200, TB>>>();
    bn_finalize_kernel<<<1, 512>>>();
    bn_relu_kernel<<<GRID_ND, TB>>>(gamma, beta);
    final_kernel<<<(NN + 7) / 8, TB>>>(lw, lb, out);
}

// round 2
// speedup vs baseline: 1.2212x; 1.2212x over previous
#include <cuda_runtime.h>
#include <math.h>

#define NN 20000
#define EE 160000
#define DD 512
#define HH 8
#define CC 64
#define LL 7
#define ND (NN*DD)

// ---------------- scratch (device globals; no allocation allowed) ----------
__device__ float    g_h[ND];        // residual stream (also final GAT output)
__device__ float    g_z[ND];        // bn+relu output
__device__ float    g_lin[ND];      // per-layer GEMM output (h_l)
__device__ float    g_sc_src[NN*HH];
__device__ float    g_sc_dst[NN*HH];
__device__ float    g_w[EE*HH];     // normalized edge weights (CSR order)
__device__ float    g_selfw[NN*HH]; // self-loop weight
__device__ int      g_deg[NN];
__device__ int      g_off[NN+1];
__device__ int      g_cur[NN];
__device__ int      g_esrc[EE];     // src node per CSR slot
__device__ float    g_sum[DD];
__device__ float    g_sq[DD];
__device__ float    g_mu[DD];
__device__ float    g_rstd[DD];

__device__ __forceinline__ float lrelu(float v) { return v > 0.f ? v : 0.2f * v; }

// ================= CSR construction (edge_index is launch-constant) ========
__global__ void hist_kernel(const int* __restrict__ ei) {
    int e = blockIdx.x * blockDim.x + threadIdx.x;
    if (e < EE) atomicAdd(&g_deg[ei[EE + e]], 1);
}

// single block, 1024 threads: exclusive scan of g_deg -> g_off, copy to g_cur
__global__ void scan_kernel() {
    __shared__ int s[1024];
    const int CH = (NN + 1023) / 1024;   // 20
    int t = threadIdx.x;
    int base = t * CH;
    int sum = 0;
    for (int i = 0; i < CH; i++) {
        int idx = base + i;
        if (idx < NN) sum += g_deg[idx];
    }
    s[t] = sum;
    __syncthreads();
    for (int o = 1; o < 1024; o <<= 1) {
        int v = (t >= o) ? s[t - o] : 0;
        __syncthreads();
        s[t] += v;
        __syncthreads();
    }
    int run = (t > 0) ? s[t - 1] : 0;
    for (int i = 0; i < CH; i++) {
        int idx = base + i;
        if (idx < NN) {
            g_off[idx] = run;
            g_cur[idx] = run;
            run += g_deg[idx];
        }
    }
    if (t == 0) g_off[NN] = s[1023];
}

__global__ void fill_kernel(const int* __restrict__ ei) {
    int e = blockIdx.x * blockDim.x + threadIdx.x;
    if (e >= EE) return;
    int s = ei[e], d = ei[EE + e];
    int pos = atomicAdd(&g_cur[d], 1);
    g_esrc[pos] = s;
}

// ---------------- SGEMM: g_lin = A[NN,512] @ B[512,512] --------------------
// 128x128 tile, BK=8, 256 threads, 8x8 per thread, float4 everywhere.
__global__ __launch_bounds__(256) void sgemm128(const float* __restrict__ A,
                                                const float* __restrict__ Bm) {
    __shared__ float As[8][128];
    __shared__ float Bs[8][128];
    int tid = threadIdx.x;
    int row0 = blockIdx.y * 128;
    int col0 = blockIdx.x * 128;
    int arow = tid >> 1;            // 0..127
    int acol = (tid & 1) * 4;       // 0 or 4
    int brow = tid >> 5;            // 0..7
    int bcol = (tid & 31) * 4;      // 0..124
    int tx = tid & 15, ty = tid >> 4;

    float acc[8][8] = {};
    float af[8], bf[8];

    for (int k0 = 0; k0 < 512; k0 += 8) {
        int r = row0 + arow;
        float4 av = make_float4(0.f, 0.f, 0.f, 0.f);
        if (r < NN) av = *(const float4*)&A[(size_t)r * 512 + k0 + acol];
        As[acol + 0][arow] = av.x; As[acol + 1][arow] = av.y;
        As[acol + 2][arow] = av.z; As[acol + 3][arow] = av.w;
        float4 bv = *(const float4*)&Bm[(size_t)(k0 + brow) * 512 + col0 + bcol];
        *(float4*)&Bs[brow][bcol] = bv;
        __syncthreads();
#pragma unroll
        for (int k = 0; k < 8; k++) {
#pragma unroll
            for (int i = 0; i < 8; i += 4) {
                float4 t4 = *(const float4*)&As[k][ty * 8 + i];
                af[i] = t4.x; af[i + 1] = t4.y; af[i + 2] = t4.z; af[i + 3] = t4.w;
            }
#pragma unroll
            for (int i = 0; i < 8; i += 4) {
                float4 t4 = *(const float4*)&Bs[k][tx * 8 + i];
                bf[i] = t4.x; bf[i + 1] = t4.y; bf[i + 2] = t4.z; bf[i + 3] = t4.w;
            }
#pragma unroll
            for (int i = 0; i < 8; i++)
#pragma unroll
                for (int j = 0; j < 8; j++)
                    acc[i][j] += af[i] * bf[j];
        }
        __syncthreads();
    }
#pragma unroll
    for (int i = 0; i < 8; i++) {
        int r = row0 + ty * 8 + i;
        if (r < NN) {
#pragma unroll
            for (int j = 0; j < 8; j += 4) {
                *(float4*)&g_lin[(size_t)r * 512 + col0 + tx * 8 + j] =
                    make_float4(acc[i][j], acc[i][j + 1], acc[i][j + 2], acc[i][j + 3]);
            }
        }
    }
}

// ---------------- attention scores: per (node, head) dot over C=64 ---------
__global__ void scores_kernel(const float* __restrict__ asrc, const float* __restrict__ adst) {
    int n = blockIdx.x;
    int w = threadIdx.x >> 5;   // head (8 warps = 8 heads)
    int lane = threadIdx.x & 31;
    const float* hp = g_lin + (size_t)n * 512 + w * 64;
    float v0 = hp[lane], v1 = hp[lane + 32];
    float ss = v0 * asrc[w * 64 + lane] + v1 * asrc[w * 64 + lane + 32];
    float sd = v0 * adst[w * 64 + lane] + v1 * adst[w * 64 + lane + 32];
#pragma unroll
    for (int o = 16; o; o >>= 1) {
        ss += __shfl_xor_sync(0xffffffffu, ss, o);
        sd += __shfl_xor_sync(0xffffffffu, sd, o);
    }
    if (!lane) { g_sc_src[n * 8 + w] = ss; g_sc_dst[n * 8 + w] = sd; }
}

// ------------- segment softmax over CSR, one thread per (dst,head) ---------
__global__ void softmax_kernel() {
    int i = blockIdx.x * blockDim.x + threadIdx.x;
    if (i >= NN * HH) return;
    int d = i >> 3, h = i & 7;
    float sdst = g_sc_dst[i];
    float self = lrelu(g_sc_src[i] + sdst);
    int o0 = g_off[d], o1 = g_off[d + 1];
    float m = self;
    for (int j = o0; j < o1; j++) {
        float a = lrelu(g_sc_src[g_esrc[j] * 8 + h] + sdst);
        m = fmaxf(m, a);
    }
    float se = expf(self - m);
    float sum = se;
    for (int j = o0; j < o1; j++) {
        float a = lrelu(g_sc_src[g_esrc[j] * 8 + h] + sdst);
        float ex = expf(a - m);
        g_w[j * 8 + h] = ex;
        sum += ex;
    }
    float inv = 1.f / (sum + 1e-16f);
    g_selfw[i] = se * inv;
    for (int j = o0; j < o1; j++) g_w[j * 8 + h] *= inv;
}

// ------------- aggregation: one block (128 thr) per dst, gather, no atomics -
// h_new[d] = (residual? h[d] : 0) + bias + selfw*lin[d] + sum_j w_j*lin[src_j]
__global__ void agg_kernel(const float* __restrict__ bias, int residual) {
    int d = blockIdx.x;
    int t = threadIdx.x;        // 0..127
    int col = t * 4;
    int h = col >> 6;
    int o0 = g_off[d], o1 = g_off[d + 1];
    float sw = g_selfw[d * 8 + h];
    float4 lv = *(const float4*)&g_lin[(size_t)d * 512 + col];
    float4 b4 = *(const float4*)&bias[col];
    float ax = b4.x + sw * lv.x;
    float ay = b4.y + sw * lv.y;
    float az = b4.z + sw * lv.z;
    float aw = b4.w + sw * lv.w;
    for (int j = o0; j < o1; j++) {
        int s = g_esrc[j];
        float w = g_w[j * 8 + h];
        float4 v = *(const float4*)&g_lin[(size_t)s * 512 + col];
        ax += w * v.x; ay += w * v.y; az += w * v.z; aw += w * v.w;
    }
    float* op = &g_h[(size_t)d * 512 + col];
    if (residual) {
        float4 hv = *(const float4*)op;
        ax += hv.x; ay += hv.y; az += hv.z; aw += hv.w;
    }
    *(float4*)op = make_float4(ax, ay, az, aw);
}

// ---------------- BN ---------------------------------------------------------
__global__ void bn_partial_kernel() {
    int t = threadIdx.x;            // 0..255
    int row0 = blockIdx.x * 100;
    float s0 = 0.f, s1 = 0.f, q0 = 0.f, q1 = 0.f;
    for (int r = 0; r < 100; r++) {
        const float* p = g_h + (size_t)(row0 + r) * 512;
        float a = p[t], b = p[t + 256];
        s0 += a; s1 += b; q0 += a * a; q1 += b * b;
    }
    atomicAdd(&g_sum[t], s0);       atomicAdd(&g_sum[t + 256], s1);
    atomicAdd(&g_sq[t], q0);        atomicAdd(&g_sq[t + 256], q1);
}

__global__ void bn_finalize_kernel() {
    int d = threadIdx.x;
    float mu = g_sum[d] * (1.f / NN);
    float var = g_sq[d] * (1.f / NN) - mu * mu;
    g_mu[d] = mu;
    g_rstd[d] = rsqrtf(var + 1e-5f);
}

__global__ void bn_relu_kernel(const float* __restrict__ gamma, const float* __restrict__ beta) {
    int i = blockIdx.x * blockDim.x + threadIdx.x;
    int d = i & 511;
    float v = gamma[d] * (g_h[i] - g_mu[d]) * g_rstd[d] + beta[d];
    g_z[i] = v > 0.f ? v : 0.f;
}

// one warp per node: out[n] = dot(z[n,:], lin_w) + lin_b
__global__ void final_kernel(const float* __restrict__ lw, const float* __restrict__ lb,
                             float* __restrict__ out) {
    int n = blockIdx.x * 8 + (threadIdx.x >> 5);
    int lane = threadIdx.x & 31;
    if (n >= NN) return;
    const float* zp = g_z + (size_t)n * 512;
    float s = 0.f;
#pragma unroll
    for (int i = 0; i < 16; i++) {
        int dd = i * 32 + lane;
        s += zp[dd] * lw[dd];
    }
#pragma unroll
    for (int o = 16; o; o >>= 1) s += __shfl_xor_sync(0xffffffffu, s, o);
    if (!lane) out[n] = s + lb[0];
}

// ---------------------------------------------------------------------------
extern "C" void kernel_launch(void* const* d_in, const int* in_sizes, int n_in,
                              void* d_out, int out_size) {
    (void)in_sizes; (void)n_in; (void)out_size;
    const float* x     = (const float*)d_in[0];
    const int*   ei    = (const int*)d_in[1];
    const float* Ws    = (const float*)d_in[2];
    const float* asrc  = (const float*)d_in[3];
    const float* adst  = (const float*)d_in[4];
    const float* cbias = (const float*)d_in[5];
    const float* gamma = (const float*)d_in[6];
    const float* beta  = (const float*)d_in[7];
    const float* lw    = (const float*)d_in[8];
    const float* lb    = (const float*)d_in[9];
    float* out = (float*)d_out;

    float *p_z, *p_sum, *p_sq;
    int *p_deg;
    cudaGetSymbolAddress((void**)&p_z,   g_z);
    cudaGetSymbolAddress((void**)&p_sum, g_sum);
    cudaGetSymbolAddress((void**)&p_sq,  g_sq);
    cudaGetSymbolAddress((void**)&p_deg, g_deg);

    const int TB = 256;
    const int GRID_NH = (NN * HH + TB - 1) / TB;   // 625
    const int GRID_E  = (EE + TB - 1) / TB;        // 625
    const int GRID_ND = ND / TB;                   // 40000
    const dim3 GEMM_GRID(4, (NN + 127) / 128);     // (4, 157)

    // ---- CSR build (edges constant; cheap, stays in the graph) ----
    cudaMemsetAsync(p_deg, 0, NN * sizeof(int));
    hist_kernel<<<GRID_E, TB>>>(ei);
    scan_kernel<<<1, 1024>>>();
    fill_kernel<<<GRID_E, TB>>>(ei);

    auto gat = [&](const float* zin, int l, int residual) {
        sgemm128<<<GEMM_GRID, TB>>>(zin, Ws + (size_t)l * 512 * 512);
        scores_kernel<<<NN, TB>>>(asrc + l * HH * CC, adst + l * HH * CC);
        softmax_kernel<<<GRID_NH, TB>>>();
        agg_kernel<<<NN, 128>>>(cbias + l * 512, residual);
    };

    // layer 0: h = gat(x)
    gat(x, 0, 0);

    // layers 1..6: h = h + gat(relu(bn(h, gamma_l, beta_l)))
    for (int l = 1; l < LL; l++) {
        cudaMemsetAsync(p_sum, 0, DD * sizeof(float));
        cudaMemsetAsync(p_sq,  0, DD * sizeof(float));
        bn_partial_kernel<<<200, TB>>>();
        bn_finalize_kernel<<<1, 512>>>();
        bn_relu_kernel<<<GRID_ND, TB>>>(gamma + l * 512, beta + l * 512);
        gat(p_z, l, 1);
    }

    // final: relu(bn(h, gamma_0, beta_0)) @ lin_w + lin_b
    cudaMemsetAsync(p_sum, 0, DD * sizeof(float));
    cudaMemsetAsync(p_sq,  0, DD * sizeof(float));
    bn_partial_kernel<<<200, TB>>>();
    bn_finalize_kernel<<<1, 512>>>();
    bn_relu_kernel<<<GRID_ND, TB>>>(gamma, beta);
    final_kernel<<<(NN + 7) / 8, TB>>>(lw, lb, out);
}

// round 3
// speedup vs baseline: 1.2225x; 1.0011x over previous
#include <cuda_runtime.h>
#include <math.h>

#define NN 20000
#define EE 160000
#define DD 512
#define HH 8
#define CC 64
#define LL 7
#define ND (NN*DD)

// ---------------- scratch (device globals; no allocation allowed) ----------
__device__ float    g_h[ND];        // residual stream (also final GAT output)
__device__ float    g_z[ND];        // bn+relu output
__device__ float    g_lin[ND];      // per-layer GEMM output (h_l)
__device__ float    g_sc_src[NN*HH];
__device__ float    g_sc_dst[NN*HH];
__device__ float    g_w[EE*HH];     // normalized edge weights (CSR order)
__device__ float    g_selfw[NN*HH]; // self-loop weight
__device__ int      g_deg[NN];
__device__ int      g_off[NN+1];
__device__ int      g_cur[NN];
__device__ int      g_esrc[EE];     // src node per CSR slot
__device__ float    g_sum[DD];
__device__ float    g_sq[DD];
__device__ float    g_mu[DD];
__device__ float    g_rstd[DD];

__device__ __forceinline__ float lrelu(float v) { return v > 0.f ? v : 0.2f * v; }

// ================= CSR construction (edge_index is launch-constant) ========
__global__ void hist_kernel(const int* __restrict__ ei) {
    int e = blockIdx.x * blockDim.x + threadIdx.x;
    if (e < EE) atomicAdd(&g_deg[ei[EE + e]], 1);
}

// single block, 1024 threads: exclusive scan of g_deg -> g_off, copy to g_cur
__global__ void scan_kernel() {
    __shared__ int s[1024];
    const int CH = (NN + 1023) / 1024;   // 20
    int t = threadIdx.x;
    int base = t * CH;
    int sum = 0;
    for (int i = 0; i < CH; i++) {
        int idx = base + i;
        if (idx < NN) sum += g_deg[idx];
    }
    s[t] = sum;
    __syncthreads();
    for (int o = 1; o < 1024; o <<= 1) {
        int v = (t >= o) ? s[t - o] : 0;
        __syncthreads();
        s[t] += v;
        __syncthreads();
    }
    int run = (t > 0) ? s[t - 1] : 0;
    for (int i = 0; i < CH; i++) {
        int idx = base + i;
        if (idx < NN) {
            g_off[idx] = run;
            g_cur[idx] = run;
            run += g_deg[idx];
        }
    }
    if (t == 0) g_off[NN] = s[1023];
}

__global__ void fill_kernel(const int* __restrict__ ei) {
    int e = blockIdx.x * blockDim.x + threadIdx.x;
    if (e >= EE) return;
    int s = ei[e], d = ei[EE + e];
    int pos = atomicAdd(&g_cur[d], 1);
    g_esrc[pos] = s;
}

// ---------------- SGEMM: g_lin = A[NN,512] @ B[512,512] --------------------
// 128x128 tile, BK=8, 256 threads, 8x8 per thread, float4 everywhere.
__global__ __launch_bounds__(256) void sgemm128(const float* __restrict__ A,
                                                const float* __restrict__ Bm) {
    __shared__ float As[8][128];
    __shared__ float Bs[8][128];
    int tid = threadIdx.x;
    int row0 = blockIdx.y * 128;
    int col0 = blockIdx.x * 128;
    int arow = tid >> 1;            // 0..127
    int acol = (tid & 1) * 4;       // 0 or 4
    int brow = tid >> 5;            // 0..7
    int bcol = (tid & 31) * 4;      // 0..124
    int tx = tid & 15, ty = tid >> 4;

    float acc[8][8] = {};
    float af[8], bf[8];

    for (int k0 = 0; k0 < 512; k0 += 8) {
        int r = row0 + arow;
        float4 av = make_float4(0.f, 0.f, 0.f, 0.f);
        if (r < NN) av = *(const float4*)&A[(size_t)r * 512 + k0 + acol];
        As[acol + 0][arow] = av.x; As[acol + 1][arow] = av.y;
        As[acol + 2][arow] = av.z; As[acol + 3][arow] = av.w;
        float4 bv = *(const float4*)&Bm[(size_t)(k0 + brow) * 512 + col0 + bcol];
        *(float4*)&Bs[brow][bcol] = bv;
        __syncthreads();
#pragma unroll
        for (int k = 0; k < 8; k++) {
#pragma unroll
            for (int i = 0; i < 8; i += 4) {
                float4 t4 = *(const float4*)&As[k][ty * 8 + i];
                af[i] = t4.x; af[i + 1] = t4.y; af[i + 2] = t4.z; af[i + 3] = t4.w;
            }
#pragma unroll
            for (int i = 0; i < 8; i += 4) {
                float4 t4 = *(const float4*)&Bs[k][tx * 8 + i];
                bf[i] = t4.x; bf[i + 1] = t4.y; bf[i + 2] = t4.z; bf[i + 3] = t4.w;
            }
#pragma unroll
            for (int i = 0; i < 8; i++)
#pragma unroll
                for (int j = 0; j < 8; j++)
                    acc[i][j] += af[i] * bf[j];
        }
        __syncthreads();
    }
#pragma unroll
    for (int i = 0; i < 8; i++) {
        int r = row0 + ty * 8 + i;
        if (r < NN) {
#pragma unroll
            for (int j = 0; j < 8; j += 4) {
                *(float4*)&g_lin[(size_t)r * 512 + col0 + tx * 8 + j] =
                    make_float4(acc[i][j], acc[i][j + 1], acc[i][j + 2], acc[i][j + 3]);
            }
        }
    }
}

// ---------------- attention scores: per (node, head) dot over C=64 ---------
__global__ void scores_kernel(const float* __restrict__ asrc, const float* __restrict__ adst) {
    int n = blockIdx.x;
    int w = threadIdx.x >> 5;   // head (8 warps = 8 heads)
    int lane = threadIdx.x & 31;
    const float* hp = g_lin + (size_t)n * 512 + w * 64;
    float v0 = hp[lane], v1 = hp[lane + 32];
    float ss = v0 * asrc[w * 64 + lane] + v1 * asrc[w * 64 + lane + 32];
    float sd = v0 * adst[w * 64 + lane] + v1 * adst[w * 64 + lane + 32];
#pragma unroll
    for (int o = 16; o; o >>= 1) {
        ss += __shfl_xor_sync(0xffffffffu, ss, o);
        sd += __shfl_xor_sync(0xffffffffu, sd, o);
    }
    if (!lane) { g_sc_src[n * 8 + w] = ss; g_sc_dst[n * 8 + w] = sd; }
}

// ------------- segment softmax over CSR, one thread per (dst,head) ---------
__global__ void softmax_kernel() {
    int i = blockIdx.x * blockDim.x + threadIdx.x;
    if (i >= NN * HH) return;
    int d = i >> 3, h = i & 7;
    float sdst = g_sc_dst[i];
    float self = lrelu(g_sc_src[i] + sdst);
    int o0 = g_off[d], o1 = g_off[d + 1];
    float m = self;
    for (int j = o0; j < o1; j++) {
        float a = lrelu(g_sc_src[g_esrc[j] * 8 + h] + sdst);
        m = fmaxf(m, a);
    }
    float se = expf(self - m);
    float sum = se;
    for (int j = o0; j < o1; j++) {
        float a = lrelu(g_sc_src[g_esrc[j] * 8 + h] + sdst);
        float ex = expf(a - m);
        g_w[j * 8 + h] = ex;
        sum += ex;
    }
    float inv = 1.f / (sum + 1e-16f);
    g_selfw[i] = se * inv;
    for (int j = o0; j < o1; j++) g_w[j * 8 + h] *= inv;
}

// ------------- aggregation: one block (128 thr) per dst, gather, no atomics -
// h_new[d] = (residual? h[d] : 0) + bias + selfw*lin[d] + sum_j w_j*lin[src_j]
__global__ void agg_kernel(const float* __restrict__ bias, int residual) {
    int d = blockIdx.x;
    int t = threadIdx.x;        // 0..127
    int col = t * 4;
    int h = col >> 6;
    int o0 = g_off[d], o1 = g_off[d + 1];
    float sw = g_selfw[d * 8 + h];
    float4 lv = *(const float4*)&g_lin[(size_t)d * 512 + col];
    float4 b4 = *(const float4*)&bias[col];
    float ax = b4.x + sw * lv.x;
    float ay = b4.y + sw * lv.y;
    float az = b4.z + sw * lv.z;
    float aw = b4.w + sw * lv.w;
    for (int j = o0; j < o1; j++) {
        int s = g_esrc[j];
        float w = g_w[j * 8 + h];
        float4 v = *(const float4*)&g_lin[(size_t)s * 512 + col];
        ax += w * v.x; ay += w * v.y; az += w * v.z; aw += w * v.w;
    }
    float* op = &g_h[(size_t)d * 512 + col];
    if (residual) {
        float4 hv = *(const float4*)op;
        ax += hv.x; ay += hv.y; az += hv.z; aw += hv.w;
    }
    *(float4*)op = make_float4(ax, ay, az, aw);
}

// ---------------- BN ---------------------------------------------------------
__global__ void bn_partial_kernel() {
    int t = threadIdx.x;            // 0..255
    int row0 = blockIdx.x * 100;
    float s0 = 0.f, s1 = 0.f, q0 = 0.f, q1 = 0.f;
    for (int r = 0; r < 100; r++) {
        const float* p = g_h + (size_t)(row0 + r) * 512;
        float a = p[t], b = p[t + 256];
        s0 += a; s1 += b; q0 += a * a; q1 += b * b;
    }
    atomicAdd(&g_sum[t], s0);       atomicAdd(&g_sum[t + 256], s1);
    atomicAdd(&g_sq[t], q0);        atomicAdd(&g_sq[t + 256], q1);
}

__global__ void bn_finalize_kernel() {
    int d = threadIdx.x;
    float mu = g_sum[d] * (1.f / NN);
    float var = g_sq[d] * (1.f / NN) - mu * mu;
    g_mu[d] = mu;
    g_rstd[d] = rsqrtf(var + 1e-5f);
}

__global__ void bn_relu_kernel(const float* __restrict__ gamma, const float* __restrict__ beta) {
    int i = blockIdx.x * blockDim.x + threadIdx.x;
    int d = i & 511;
    float v = gamma[d] * (g_h[i] - g_mu[d]) * g_rstd[d] + beta[d];
    g_z[i] = v > 0.f ? v : 0.f;
}

// one warp per node: out[n] = dot(z[n,:], lin_w) + lin_b
__global__ void final_kernel(const float* __restrict__ lw, const float* __restrict__ lb,
                             float* __restrict__ out) {
    int n = blockIdx.x * 8 + (threadIdx.x >> 5);
    int lane = threadIdx.x & 31;
    if (n >= NN) return;
    const float* zp = g_z + (size_t)n * 512;
    float s = 0.f;
#pragma unroll
    for (int i = 0; i < 16; i++) {
        int dd = i * 32 + lane;
        s += zp[dd] * lw[dd];
    }
#pragma unroll
    for (int o = 16; o; o >>= 1) s += __shfl_xor_sync(0xffffffffu, s, o);
    if (!lane) out[n] = s + lb[0];
}

// ---------------------------------------------------------------------------
extern "C" void kernel_launch(void* const* d_in, const int* in_sizes, int n_in,
                              void* d_out, int out_size) {
    (void)in_sizes; (void)n_in; (void)out_size;
    const float* x     = (const float*)d_in[0];
    const int*   ei    = (const int*)d_in[1];
    const float* Ws    = (const float*)d_in[2];
    const float* asrc  = (const float*)d_in[3];
    const float* adst  = (const float*)d_in[4];
    const float* cbias = (const float*)d_in[5];
    const float* gamma = (const float*)d_in[6];
    const float* beta  = (const float*)d_in[7];
    const float* lw    = (const float*)d_in[8];
    const float* lb    = (const float*)d_in[9];
    float* out = (float*)d_out;

    float *p_z, *p_sum, *p_sq;
    int *p_deg;
    cudaGetSymbolAddress((void**)&p_z,   g_z);
    cudaGetSymbolAddress((void**)&p_sum, g_sum);
    cudaGetSymbolAddress((void**)&p_sq,  g_sq);
    cudaGetSymbolAddress((void**)&p_deg, g_deg);

    const int TB = 256;
    const int GRID_NH = (NN * HH + TB - 1) / TB;   // 625
    const int GRID_E  = (EE + TB - 1) / TB;        // 625
    const int GRID_ND = ND / TB;                   // 40000
    const dim3 GEMM_GRID(4, (NN + 127) / 128);     // (4, 157)

    // ---- CSR build (edges constant; cheap, stays in the graph) ----
    cudaMemsetAsync(p_deg, 0, NN * sizeof(int));
    hist_kernel<<<GRID_E, TB>>>(ei);
    scan_kernel<<<1, 1024>>>();
    fill_kernel<<<GRID_E, TB>>>(ei);

    auto gat = [&](const float* zin, int l, int residual) {
        sgemm128<<<GEMM_GRID, TB>>>(zin, Ws + (size_t)l * 512 * 512);
        scores_kernel<<<NN, TB>>>(asrc + l * HH * CC, adst + l * HH * CC);
        softmax_kernel<<<GRID_NH, TB>>>();
        agg_kernel<<<NN, 128>>>(cbias + l * 512, residual);
    };

    // layer 0: h = gat(x)
    gat(x, 0, 0);

    // layers 1..6: h = h + gat(relu(bn(h, gamma_l, beta_l)))
    for (int l = 1; l < LL; l++) {
        cudaMemsetAsync(p_sum, 0, DD * sizeof(float));
        cudaMemsetAsync(p_sq,  0, DD * sizeof(float));
        bn_partial_kernel<<<200, TB>>>();
        bn_finalize_kernel<<<1, 512>>>();
        bn_relu_kernel<<<GRID_ND, TB>>>(gamma + l * 512, beta + l * 512);
        gat(p_z, l, 1);
    }

    // final: relu(bn(h, gamma_0, beta_0)) @ lin_w + lin_b
    cudaMemsetAsync(p_sum, 0, DD * sizeof(float));
    cudaMemsetAsync(p_sq,  0, DD * sizeof(float));
    bn_partial_kernel<<<200, TB>>>();
    bn_finalize_kernel<<<1, 512>>>();
    bn_relu_kernel<<<GRID_ND, TB>>>(gamma, beta);
    final_kernel<<<(NN + 7) / 8, TB>>>(lw, lb, out);
}

// round 4
// speedup vs baseline: 1.2230x; 1.0004x over previous
#include <cuda_runtime.h>
#include <math.h>

#define NN 20000
#define EE 160000
#define DD 512
#define HH 8
#define CC 64
#define LL 7
#define ND (NN*DD)

// ---------------- scratch (device globals; no allocation allowed) ----------
__device__ float    g_h[ND];        // residual stream (also final GAT output)
__device__ float    g_z[ND];        // bn+relu output
__device__ float    g_lin[ND];      // per-layer GEMM output (h_l)
__device__ float    g_sc_src[NN*HH];
__device__ float    g_sc_dst[NN*HH];
__device__ float    g_w[EE*HH];     // normalized edge weights (CSR order)
__device__ float    g_selfw[NN*HH]; // self-loop weight
__device__ int      g_deg[NN];
__device__ int      g_off[NN+1];
__device__ int      g_cur[NN];
__device__ int      g_esrc[EE];     // src node per CSR slot
__device__ float    g_sum[DD];
__device__ float    g_sq[DD];
__device__ float    g_mu[DD];
__device__ float    g_rstd[DD];

__device__ __forceinline__ float lrelu(float v) { return v > 0.f ? v : 0.2f * v; }

// ================= CSR construction (edge_index is launch-constant) ========
__global__ void hist_kernel(const int* __restrict__ ei) {
    int e = blockIdx.x * blockDim.x + threadIdx.x;
    if (e < EE) atomicAdd(&g_deg[ei[EE + e]], 1);
}

// single block, 1024 threads: exclusive scan of g_deg -> g_off, copy to g_cur
__global__ void scan_kernel() {
    __shared__ int s[1024];
    const int CH = (NN + 1023) / 1024;   // 20
    int t = threadIdx.x;
    int base = t * CH;
    int sum = 0;
    for (int i = 0; i < CH; i++) {
        int idx = base + i;
        if (idx < NN) sum += g_deg[idx];
    }
    s[t] = sum;
    __syncthreads();
    for (int o = 1; o < 1024; o <<= 1) {
        int v = (t >= o) ? s[t - o] : 0;
        __syncthreads();
        s[t] += v;
        __syncthreads();
    }
    int run = (t > 0) ? s[t - 1] : 0;
    for (int i = 0; i < CH; i++) {
        int idx = base + i;
        if (idx < NN) {
            g_off[idx] = run;
            g_cur[idx] = run;
            run += g_deg[idx];
        }
    }
    if (t == 0) g_off[NN] = s[1023];
}

__global__ void fill_kernel(const int* __restrict__ ei) {
    int e = blockIdx.x * blockDim.x + threadIdx.x;
    if (e >= EE) return;
    int s = ei[e], d = ei[EE + e];
    int pos = atomicAdd(&g_cur[d], 1);
    g_esrc[pos] = s;
}

// ---------------- SGEMM: g_lin = A[NN,512] @ B[512,512] --------------------
// 128x128 tile, BK=8, 256 threads, 8x8 per thread, float4 everywhere.
__global__ __launch_bounds__(256) void sgemm128(const float* __restrict__ A,
                                                const float* __restrict__ Bm) {
    __shared__ float As[8][128];
    __shared__ float Bs[8][128];
    int tid = threadIdx.x;
    int row0 = blockIdx.y * 128;
    int col0 = blockIdx.x * 128;
    int arow = tid >> 1;            // 0..127
    int acol = (tid & 1) * 4;       // 0 or 4
    int brow = tid >> 5;            // 0..7
    int bcol = (tid & 31) * 4;      // 0..124
    int tx = tid & 15, ty = tid >> 4;

    float acc[8][8] = {};
    float af[8], bf[8];

    for (int k0 = 0; k0 < 512; k0 += 8) {
        int r = row0 + arow;
        float4 av = make_float4(0.f, 0.f, 0.f, 0.f);
        if (r < NN) av = *(const float4*)&A[(size_t)r * 512 + k0 + acol];
        As[acol + 0][arow] = av.x; As[acol + 1][arow] = av.y;
        As[acol + 2][arow] = av.z; As[acol + 3][arow] = av.w;
        float4 bv = *(const float4*)&Bm[(size_t)(k0 + brow) * 512 + col0 + bcol];
        *(float4*)&Bs[brow][bcol] = bv;
        __syncthreads();
#pragma unroll
        for (int k = 0; k < 8; k++) {
#pragma unroll
            for (int i = 0; i < 8; i += 4) {
                float4 t4 = *(const float4*)&As[k][ty * 8 + i];
                af[i] = t4.x; af[i + 1] = t4.y; af[i + 2] = t4.z; af[i + 3] = t4.w;
            }
#pragma unroll
            for (int i = 0; i < 8; i += 4) {
                float4 t4 = *(const float4*)&Bs[k][tx * 8 + i];
                bf[i] = t4.x; bf[i + 1] = t4.y; bf[i + 2] = t4.z; bf[i + 3] = t4.w;
            }
#pragma unroll
            for (int i = 0; i < 8; i++)
#pragma unroll
                for (int j = 0; j < 8; j++)
                    acc[i][j] += af[i] * bf[j];
        }
        __syncthreads();
    }
#pragma unroll
    for (int i = 0; i < 8; i++) {
        int r = row0 + ty * 8 + i;
        if (r < NN) {
#pragma unroll
            for (int j = 0; j < 8; j += 4) {
                *(float4*)&g_lin[(size_t)r * 512 + col0 + tx * 8 + j] =
                    make_float4(acc[i][j], acc[i][j + 1], acc[i][j + 2], acc[i][j + 3]);
            }
        }
    }
}

// ---------------- attention scores: per (node, head) dot over C=64 ---------
__global__ void scores_kernel(const float* __restrict__ asrc, const float* __restrict__ adst) {
    int n = blockIdx.x;
    int w = threadIdx.x >> 5;   // head (8 warps = 8 heads)
    int lane = threadIdx.x & 31;
    const float* hp = g_lin + (size_t)n * 512 + w * 64;
    float v0 = hp[lane], v1 = hp[lane + 32];
    float ss = v0 * asrc[w * 64 + lane] + v1 * asrc[w * 64 + lane + 32];
    float sd = v0 * adst[w * 64 + lane] + v1 * adst[w * 64 + lane + 32];
#pragma unroll
    for (int o = 16; o; o >>= 1) {
        ss += __shfl_xor_sync(0xffffffffu, ss, o);
        sd += __shfl_xor_sync(0xffffffffu, sd, o);
    }
    if (!lane) { g_sc_src[n * 8 + w] = ss; g_sc_dst[n * 8 + w] = sd; }
}

// ------------- segment softmax over CSR, one thread per (dst,head) ---------
__global__ void softmax_kernel() {
    int i = blockIdx.x * blockDim.x + threadIdx.x;
    if (i >= NN * HH) return;
    int d = i >> 3, h = i & 7;
    float sdst = g_sc_dst[i];
    float self = lrelu(g_sc_src[i] + sdst);
    int o0 = g_off[d], o1 = g_off[d + 1];
    float m = self;
    for (int j = o0; j < o1; j++) {
        float a = lrelu(g_sc_src[g_esrc[j] * 8 + h] + sdst);
        m = fmaxf(m, a);
    }
    float se = expf(self - m);
    float sum = se;
    for (int j = o0; j < o1; j++) {
        float a = lrelu(g_sc_src[g_esrc[j] * 8 + h] + sdst);
        float ex = expf(a - m);
        g_w[j * 8 + h] = ex;
        sum += ex;
    }
    float inv = 1.f / (sum + 1e-16f);
    g_selfw[i] = se * inv;
    for (int j = o0; j < o1; j++) g_w[j * 8 + h] *= inv;
}

// ------------- aggregation: one block (128 thr) per dst, gather, no atomics -
// h_new[d] = (residual? h[d] : 0) + bias + selfw*lin[d] + sum_j w_j*lin[src_j]
__global__ void agg_kernel(const float* __restrict__ bias, int residual) {
    int d = blockIdx.x;
    int t = threadIdx.x;        // 0..127
    int col = t * 4;
    int h = col >> 6;
    int o0 = g_off[d], o1 = g_off[d + 1];
    float sw = g_selfw[d * 8 + h];
    float4 lv = *(const float4*)&g_lin[(size_t)d * 512 + col];
    float4 b4 = *(const float4*)&bias[col];
    float ax = b4.x + sw * lv.x;
    float ay = b4.y + sw * lv.y;
    float az = b4.z + sw * lv.z;
    float aw = b4.w + sw * lv.w;
    for (int j = o0; j < o1; j++) {
        int s = g_esrc[j];
        float w = g_w[j * 8 + h];
        float4 v = *(const float4*)&g_lin[(size_t)s * 512 + col];
        ax += w * v.x; ay += w * v.y; az += w * v.z; aw += w * v.w;
    }
    float* op = &g_h[(size_t)d * 512 + col];
    if (residual) {
        float4 hv = *(const float4*)op;
        ax += hv.x; ay += hv.y; az += hv.z; aw += hv.w;
    }
    *(float4*)op = make_float4(ax, ay, az, aw);
}

// ---------------- BN ---------------------------------------------------------
__global__ void bn_partial_kernel() {
    int t = threadIdx.x;            // 0..255
    int row0 = blockIdx.x * 100;
    float s0 = 0.f, s1 = 0.f, q0 = 0.f, q1 = 0.f;
    for (int r = 0; r < 100; r++) {
        const float* p = g_h + (size_t)(row0 + r) * 512;
        float a = p[t], b = p[t + 256];
        s0 += a; s1 += b; q0 += a * a; q1 += b * b;
    }
    atomicAdd(&g_sum[t], s0);       atomicAdd(&g_sum[t + 256], s1);
    atomicAdd(&g_sq[t], q0);        atomicAdd(&g_sq[t + 256], q1);
}

__global__ void bn_finalize_kernel() {
    int d = threadIdx.x;
    float mu = g_sum[d] * (1.f / NN);
    float var = g_sq[d] * (1.f / NN) - mu * mu;
    g_mu[d] = mu;
    g_rstd[d] = rsqrtf(var + 1e-5f);
}

__global__ void bn_relu_kernel(const float* __restrict__ gamma, const float* __restrict__ beta) {
    int i = blockIdx.x * blockDim.x + threadIdx.x;
    int d = i & 511;
    float v = gamma[d] * (g_h[i] - g_mu[d]) * g_rstd[d] + beta[d];
    g_z[i] = v > 0.f ? v : 0.f;
}

// one warp per node: out[n] = dot(z[n,:], lin_w) + lin_b
__global__ void final_kernel(const float* __restrict__ lw, const float* __restrict__ lb,
                             float* __restrict__ out) {
    int n = blockIdx.x * 8 + (threadIdx.x >> 5);
    int lane = threadIdx.x & 31;
    if (n >= NN) return;
    const float* zp = g_z + (size_t)n * 512;
    float s = 0.f;
#pragma unroll
    for (int i = 0; i < 16; i++) {
        int dd = i * 32 + lane;
        s += zp[dd] * lw[dd];
    }
#pragma unroll
    for (int o = 16; o; o >>= 1) s += __shfl_xor_sync(0xffffffffu, s, o);
    if (!lane) out[n] = s + lb[0];
}

// ---------------------------------------------------------------------------
extern "C" void kernel_launch(void* const* d_in, const int* in_sizes, int n_in,
                              void* d_out, int out_size) {
    (void)in_sizes; (void)n_in; (void)out_size;
    const float* x     = (const float*)d_in[0];
    const int*   ei    = (const int*)d_in[1];
    const float* Ws    = (const float*)d_in[2];
    const float* asrc  = (const float*)d_in[3];
    const float* adst  = (const float*)d_in[4];
    const float* cbias = (const float*)d_in[5];
    const float* gamma = (const float*)d_in[6];
    const float* beta  = (const float*)d_in[7];
    const float* lw    = (const float*)d_in[8];
    const float* lb    = (const float*)d_in[9];
    float* out = (float*)d_out;

    float *p_z, *p_sum, *p_sq;
    int *p_deg;
    cudaGetSymbolAddress((void**)&p_z,   g_z);
    cudaGetSymbolAddress((void**)&p_sum, g_sum);
    cudaGetSymbolAddress((void**)&p_sq,  g_sq);
    cudaGetSymbolAddress((void**)&p_deg, g_deg);

    const int TB = 256;
    const int GRID_NH = (NN * HH + TB - 1) / TB;   // 625
    const int GRID_E  = (EE + TB - 1) / TB;        // 625
    const int GRID_ND = ND / TB;                   // 40000
    const dim3 GEMM_GRID(4, (NN + 127) / 128);     // (4, 157)

    // ---- CSR build (edges constant; cheap, stays in the graph) ----
    cudaMemsetAsync(p_deg, 0, NN * sizeof(int));
    hist_kernel<<<GRID_E, TB>>>(ei);
    scan_kernel<<<1, 1024>>>();
    fill_kernel<<<GRID_E, TB>>>(ei);

    auto gat = [&](const float* zin, int l, int residual) {
        sgemm128<<<GEMM_GRID, TB>>>(zin, Ws + (size_t)l * 512 * 512);
        scores_kernel<<<NN, TB>>>(asrc + l * HH * CC, adst + l * HH * CC);
        softmax_kernel<<<GRID_NH, TB>>>();
        agg_kernel<<<NN, 128>>>(cbias + l * 512, residual);
    };

    // layer 0: h = gat(x)
    gat(x, 0, 0);

    // layers 1..6: h = h + gat(relu(bn(h, gamma_l, beta_l)))
    for (int l = 1; l < LL; l++) {
        cudaMemsetAsync(p_sum, 0, DD * sizeof(float));
        cudaMemsetAsync(p_sq,  0, DD * sizeof(float));
        bn_partial_kernel<<<200, TB>>>();
        bn_finalize_kernel<<<1, 512>>>();
        bn_relu_kernel<<<GRID_ND, TB>>>(gamma + l * 512, beta + l * 512);
        gat(p_z, l, 1);
    }

    // final: relu(bn(h, gamma_0, beta_0)) @ lin_w + lin_b
    cudaMemsetAsync(p_sum, 0, DD * sizeof(float));
    cudaMemsetAsync(p_sq,  0, DD * sizeof(float));
    bn_partial_kernel<<<200, TB>>>();
    bn_finalize_kernel<<<1, 512>>>();
    bn_relu_kernel<<<GRID_ND, TB>>>(gamma, beta);
    final_kernel<<<(NN + 7) / 8, TB>>>(lw, lb, out);
}